// round 3
// baseline (speedup 1.0000x reference)
#include <cuda_runtime.h>
#include <cstdint>

#define NEG_BIG (-9000000000000000.0f)
#define LEAKY 0.2f

// ---- scratch (static device globals; no runtime allocation) ----
__device__ float    g_Wh [8ul * 2048 * 256];   // fp32 Wh (exact, for s1/s2)
__device__ float    g_Whr[8ul * 2048 * 256];   // tf32-rounded Wh (B operand)
__device__ float    g_s1 [8 * 2048];
__device__ float    g_s2 [8 * 2048];
__device__ float    g_m  [8 * 2048];
__device__ float    g_ri [8 * 2048];
__device__ unsigned g_adjb[8ul * 2048 * 64];   // adj bitmask: bit l of word w = adj[row][w*32+l]

__device__ __forceinline__ float f2tf32(float x) {
    uint32_t u;
    asm("cvt.rna.tf32.f32 %0, %1;" : "=r"(u) : "f"(x));
    return __uint_as_float(u);
}

__device__ __forceinline__ unsigned sptr(const void* p) {
    return (unsigned)__cvta_generic_to_shared(p);
}
#define CP_ASYNC16(dst, src) \
    asm volatile("cp.async.cg.shared.global [%0], [%1], 16;" :: "r"(dst), "l"(src))
#define CP_COMMIT() asm volatile("cp.async.commit_group;")
#define CP_WAIT0()  asm volatile("cp.async.wait_group 0;")

// ============================================================
// Kernel 1: Wh = h @ W^T  (fp32 SIMT, 128x64 tile, 8x4/thread)
//   Writes exact fp32 g_Wh and tf32-rounded g_Whr.
// ============================================================
__global__ __launch_bounds__(256) void k_gemm(const float* __restrict__ A,
                                              const float* __restrict__ Bm) {
    __shared__ float As[16][132];
    __shared__ float Bs[16][68];

    int tid = threadIdx.x;
    int tx = tid & 15, ty = tid >> 4;          // tx: 16 col groups, ty: 16 row groups
    int m0 = blockIdx.x * 128;
    int n0 = blockIdx.y * 64;

    float acc[8][4];
#pragma unroll
    for (int i = 0; i < 8; i++)
#pragma unroll
        for (int j = 0; j < 4; j++) acc[i][j] = 0.0f;

    for (int k0 = 0; k0 < 256; k0 += 16) {
        // A tile: 128 rows x 16 k  (512 float4, 2 per thread)
#pragma unroll
        for (int p = 0; p < 2; p++) {
            int idx = tid + p * 256;
            int row = idx >> 2, c4 = (idx & 3) * 4;
            float4 v = *(const float4*)(A + (size_t)(m0 + row) * 256 + k0 + c4);
            As[c4 + 0][row] = v.x; As[c4 + 1][row] = v.y;
            As[c4 + 2][row] = v.z; As[c4 + 3][row] = v.w;
        }
        // B tile: 64 rows(n) x 16 k  (256 float4, 1 per thread)
        {
            int row = tid >> 2, c4 = (tid & 3) * 4;
            float4 v = *(const float4*)(Bm + (size_t)(n0 + row) * 256 + k0 + c4);
            Bs[c4 + 0][row] = v.x; Bs[c4 + 1][row] = v.y;
            Bs[c4 + 2][row] = v.z; Bs[c4 + 3][row] = v.w;
        }
        __syncthreads();

#pragma unroll
        for (int k = 0; k < 16; k++) {
            float4 a0 = *(const float4*)&As[k][ty * 8];
            float4 a1 = *(const float4*)&As[k][ty * 8 + 4];
            float4 b4 = *(const float4*)&Bs[k][tx * 4];
            float am[8] = {a0.x, a0.y, a0.z, a0.w, a1.x, a1.y, a1.z, a1.w};
            float bn[4] = {b4.x, b4.y, b4.z, b4.w};
#pragma unroll
            for (int i = 0; i < 8; i++)
#pragma unroll
                for (int j = 0; j < 4; j++)
                    acc[i][j] = fmaf(am[i], bn[j], acc[i][j]);
        }
        __syncthreads();
    }

#pragma unroll
    for (int i = 0; i < 8; i++) {
        size_t off = (size_t)(m0 + ty * 8 + i) * 256 + n0 + tx * 4;
        *(float4*)(g_Wh + off) =
            make_float4(acc[i][0], acc[i][1], acc[i][2], acc[i][3]);
        *(float4*)(g_Whr + off) =
            make_float4(f2tf32(acc[i][0]), f2tf32(acc[i][1]),
                        f2tf32(acc[i][2]), f2tf32(acc[i][3]));
    }
}

// ============================================================
// Kernel 2: s1[r] = Wh[r,:]·a1 ; s2[r] = Wh[r,:]·a2
// ============================================================
__global__ void k_s(const float* __restrict__ a) {
    int row  = blockIdx.x * 8 + (threadIdx.x >> 5);
    int lane = threadIdx.x & 31;
    const float* wh = g_Wh + (size_t)row * 256;

    float v1 = 0.0f, v2 = 0.0f;
#pragma unroll
    for (int k = lane; k < 256; k += 32) {
        float x = wh[k];
        v1 = fmaf(x, a[k],       v1);
        v2 = fmaf(x, a[256 + k], v2);
    }
#pragma unroll
    for (int off = 16; off; off >>= 1) {
        v1 += __shfl_down_sync(0xffffffffu, v1, off);
        v2 += __shfl_down_sync(0xffffffffu, v2, off);
    }
    if (lane == 0) { g_s1[row] = v1; g_s2[row] = v2; }
}

// ============================================================
// Kernel 3: per-row stats (max, 1/sum) + adjacency bitmask.
//   Warp per row; lane reads col c*32+lane (coalesced 128B).
// ============================================================
__global__ __launch_bounds__(256) void k_stats(const int* __restrict__ adj) {
    __shared__ float s2s[2048];

    int b    = blockIdx.y;
    int wid  = threadIdx.x >> 5;
    int lane = threadIdx.x & 31;
    int row  = blockIdx.x * 8 + wid;

    for (int k = threadIdx.x; k < 2048; k += 256) s2s[k] = g_s2[(size_t)b * 2048 + k];
    __syncthreads();

    const int* arow = adj + ((size_t)b * 2048 + row) * 2048;
    float s1i = g_s1[(size_t)b * 2048 + row];

    float m = -INFINITY, sum = 0.0f;
    unsigned wlo = 0, whi = 0;

#pragma unroll 4
    for (int c = 0; c < 64; c++) {
        int   av = arow[c * 32 + lane];
        float e  = s1i + s2s[c * 32 + lane];
        e = (e > 0.0f) ? e : LEAKY * e;
        bool  msk = (av != 0);
        float em  = msk ? e : NEG_BIG;
        if (em <= m) {
            sum += __expf(em - m);
        } else {
            sum = sum * __expf(m - em) + 1.0f;
            m = em;
        }
        unsigned bw = __ballot_sync(0xffffffffu, msk);
        if (c < 32) { if (lane == c)      wlo = bw; }
        else        { if (lane == c - 32) whi = bw; }
    }

#pragma unroll
    for (int off = 16; off; off >>= 1) {
        float om = __shfl_down_sync(0xffffffffu, m,   off);
        float os = __shfl_down_sync(0xffffffffu, sum, off);
        float nm = fmaxf(m, om);
        sum = sum * __expf(m - nm) + os * __expf(om - nm);
        m = nm;
    }
    m   = __shfl_sync(0xffffffffu, m,   0);
    sum = __shfl_sync(0xffffffffu, sum, 0);

    unsigned* bm = g_adjb + ((size_t)b * 2048 + row) * 64;
    bm[lane]      = wlo;
    bm[lane + 32] = whi;
    if (lane == 0) {
        g_m [(size_t)b * 2048 + row] = m;
        g_ri[(size_t)b * 2048 + row] = 1.0f / sum;
    }
}

// ============================================================
// Kernel 4: out = elu( softmax-weights @ Wh ) fused, tf32 mma.
//   BM=64, BN=256, BK=16. Double-buffered, cp.async B operand.
//   A operand built in-register from bitmask + exp.
// ============================================================
__device__ __forceinline__ void mma_tf32(float* d, const float* a, const float* b) {
    asm volatile(
        "mma.sync.aligned.m16n8k8.row.col.f32.tf32.tf32.f32 "
        "{%0,%1,%2,%3}, {%4,%5,%6,%7}, {%8,%9}, {%0,%1,%2,%3};"
        : "+f"(d[0]), "+f"(d[1]), "+f"(d[2]), "+f"(d[3])
        : "r"(__float_as_uint(a[0])), "r"(__float_as_uint(a[1])),
          "r"(__float_as_uint(a[2])), "r"(__float_as_uint(a[3])),
          "r"(__float_as_uint(b[0])), "r"(__float_as_uint(b[1])));
}

__global__ __launch_bounds__(256) void k_fused(float* __restrict__ out) {
    __shared__ float As[2][64][20];
    __shared__ float Bs[2][16][264];

    int b  = blockIdx.y;
    int m0 = blockIdx.x * 64;
    int tid  = threadIdx.x;
    int wid  = tid >> 5, lane = tid & 31;
    int g = lane >> 2, tig = lane & 3;
    int warpM = wid >> 2, warpN = wid & 3;

    // per-thread row constants (ar fixed for whole k-loop)
    int ar = tid >> 2;
    int ac = (tid & 3) * 4;
    int row = m0 + ar;
    float s1i  = g_s1[(size_t)b * 2048 + row];
    float mrow = g_m [(size_t)b * 2048 + row];
    float rinv = g_ri[(size_t)b * 2048 + row];
    const unsigned* bmrow = g_adjb + ((size_t)b * 2048 + row) * 64;
    const float*    s2g   = g_s2   + (size_t)b * 2048;
    const float*    Whb   = g_Whr  + (size_t)b * 2048 * 256;

    float acc[2][8][4];
#pragma unroll
    for (int mt = 0; mt < 2; mt++)
#pragma unroll
        for (int nt = 0; nt < 8; nt++)
#pragma unroll
            for (int c = 0; c < 4; c++) acc[mt][nt][c] = 0.0f;

    // ---- helpers inlined via lambdas ----
    auto buildA = [&](int k0, int buf) {
        unsigned w = bmrow[(k0 + ac) >> 5];
        int sh = (k0 + ac) & 31;
        float4 sv = *(const float4*)(s2g + k0 + ac);
        float e0 = s1i + sv.x, e1 = s1i + sv.y, e2 = s1i + sv.z, e3 = s1i + sv.w;
        e0 = (e0 > 0.0f) ? e0 : LEAKY * e0;
        e1 = (e1 > 0.0f) ? e1 : LEAKY * e1;
        e2 = (e2 > 0.0f) ? e2 : LEAKY * e2;
        e3 = (e3 > 0.0f) ? e3 : LEAKY * e3;
        float p0 = ((w >> (sh + 0)) & 1u) ? __expf(e0 - mrow) * rinv : 0.0f;
        float p1 = ((w >> (sh + 1)) & 1u) ? __expf(e1 - mrow) * rinv : 0.0f;
        float p2 = ((w >> (sh + 2)) & 1u) ? __expf(e2 - mrow) * rinv : 0.0f;
        float p3 = ((w >> (sh + 3)) & 1u) ? __expf(e3 - mrow) * rinv : 0.0f;
        As[buf][ar][ac + 0] = f2tf32(p0);
        As[buf][ar][ac + 1] = f2tf32(p1);
        As[buf][ar][ac + 2] = f2tf32(p2);
        As[buf][ar][ac + 3] = f2tf32(p3);
    };
    auto loadB = [&](int k0, int buf) {
#pragma unroll
        for (int p = 0; p < 4; p++) {
            int idx  = tid + p * 256;
            int brow = idx >> 6;
            int bcol = (idx & 63) * 4;
            CP_ASYNC16(sptr(&Bs[buf][brow][bcol]),
                       Whb + (size_t)(k0 + brow) * 256 + bcol);
        }
        CP_COMMIT();
    };

    // prologue
    buildA(0, 0);
    loadB(0, 0);

#pragma unroll 1
    for (int t = 0; t < 128; t++) {
        int cur = t & 1;
        CP_WAIT0();
        __syncthreads();
        if (t + 1 < 128) {
            buildA((t + 1) * 16, cur ^ 1);
            loadB((t + 1) * 16, cur ^ 1);
        }

#pragma unroll
        for (int kc = 0; kc < 2; kc++) {
            int kb = kc * 8;
            float afr[2][4];
#pragma unroll
            for (int mt = 0; mt < 2; mt++) {
                int mrow_ = warpM * 32 + mt * 16;
                afr[mt][0] = As[cur][mrow_ + g    ][kb + tig    ];
                afr[mt][1] = As[cur][mrow_ + g + 8][kb + tig    ];
                afr[mt][2] = As[cur][mrow_ + g    ][kb + tig + 4];
                afr[mt][3] = As[cur][mrow_ + g + 8][kb + tig + 4];
            }
            float bfr[8][2];
#pragma unroll
            for (int nt = 0; nt < 8; nt++) {
                int ncol = warpN * 64 + nt * 8 + g;
                bfr[nt][0] = Bs[cur][kb + tig    ][ncol];
                bfr[nt][1] = Bs[cur][kb + tig + 4][ncol];
            }
#pragma unroll
            for (int mt = 0; mt < 2; mt++)
#pragma unroll
                for (int nt = 0; nt < 8; nt++)
                    mma_tf32(acc[mt][nt], afr[mt], bfr[nt]);
        }
    }

    // epilogue: ELU + store
#pragma unroll
    for (int mt = 0; mt < 2; mt++) {
#pragma unroll
        for (int nt = 0; nt < 8; nt++) {
            int m = m0 + warpM * 32 + mt * 16 + g;
            int n = warpN * 64 + nt * 8 + 2 * tig;
            float c0 = acc[mt][nt][0], c1 = acc[mt][nt][1];
            float c2 = acc[mt][nt][2], c3 = acc[mt][nt][3];
            c0 = (c0 > 0.0f) ? c0 : expm1f(c0);
            c1 = (c1 > 0.0f) ? c1 : expm1f(c1);
            c2 = (c2 > 0.0f) ? c2 : expm1f(c2);
            c3 = (c3 > 0.0f) ? c3 : expm1f(c3);
            float* o0 = out + ((size_t)b * 2048 + m) * 256 + n;
            float* o1 = out + ((size_t)b * 2048 + m + 8) * 256 + n;
            *(float2*)o0 = make_float2(c0, c1);
            *(float2*)o1 = make_float2(c2, c3);
        }
    }
}

// ============================================================
extern "C" void kernel_launch(void* const* d_in, const int* in_sizes, int n_in,
                              void* d_out, int out_size) {
    const float* h   = (const float*)d_in[0];
    const int*   adj = (const int*)  d_in[1];
    const float* W   = (const float*)d_in[2];
    const float* a   = (const float*)d_in[3];
    float* out = (float*)d_out;

    dim3 g1(16384 / 128, 256 / 64);          // 128 x 4
    k_gemm<<<g1, 256>>>(h, W);

    k_s<<<16384 / 8, 256>>>(a);

    dim3 g2(2048 / 8, 8);                    // 256 x 8
    k_stats<<<g2, 256>>>(adj);

    dim3 g3(2048 / 64, 8);                   // 32 x 8
    k_fused<<<g3, 256>>>(out);
}

// round 5
// speedup vs baseline: 1.6134x; 1.6134x over previous
#include <cuda_runtime.h>
#include <cuda_fp16.h>
#include <cstdint>

#define NEG_BIG (-9000000000000000.0f)
#define LEAKY 0.2f

// ---- scratch (static device globals; no runtime allocation) ----
__device__ float  g_Wh  [8ul * 2048 * 256];    // fp32 Wh (exact, for s1/s2)
__device__ __half g_WhT [8ul * 256 * 2048];    // [b][n][k] half (B operand)
__device__ __half g_P   [8ul * 2048 * 2048];   // normalized attention, half
__device__ float  g_s1  [8 * 2048];
__device__ float  g_s2  [8 * 2048];

__device__ __forceinline__ unsigned sptr(const void* p) {
    return (unsigned)__cvta_generic_to_shared(p);
}
#define CP_ASYNC16(dst, src) \
    asm volatile("cp.async.cg.shared.global [%0], [%1], 16;" :: "r"(dst), "l"(src))
#define CP_COMMIT() asm volatile("cp.async.commit_group;")
#define CP_WAIT0()  asm volatile("cp.async.wait_group 0;")

// ============================================================
// Kernel 1: Wh = h @ W^T (fp32 SIMT 64x64) ; writes fp32 Wh and
//           half transposed WhT[b][n][k].
// ============================================================
__global__ __launch_bounds__(256) void k_gemm(const float* __restrict__ A,
                                              const float* __restrict__ Bm) {
    const int BK = 16;
    __shared__ float As[BK][68];
    __shared__ float Bs[BK][68];
    __shared__ float Cs[64][65];

    int tid = threadIdx.x;
    int tx = tid & 15, ty = tid >> 4;
    int m0 = blockIdx.x * 64;
    int n0 = blockIdx.y * 64;

    int lr = tid >> 2;
    int lc = (tid & 3) * 4;
    const float* Aptr = A  + (size_t)(m0 + lr) * 256 + lc;
    const float* Bptr = Bm + (size_t)(n0 + lr) * 256 + lc;

    float acc[4][4];
#pragma unroll
    for (int i = 0; i < 4; i++)
#pragma unroll
        for (int j = 0; j < 4; j++) acc[i][j] = 0.0f;

    for (int k0 = 0; k0 < 256; k0 += BK) {
        float4 va = *(const float4*)(Aptr + k0);
        float4 vb = *(const float4*)(Bptr + k0);
        As[lc + 0][lr] = va.x; As[lc + 1][lr] = va.y;
        As[lc + 2][lr] = va.z; As[lc + 3][lr] = va.w;
        Bs[lc + 0][lr] = vb.x; Bs[lc + 1][lr] = vb.y;
        Bs[lc + 2][lr] = vb.z; Bs[lc + 3][lr] = vb.w;
        __syncthreads();

#pragma unroll
        for (int k = 0; k < BK; k++) {
            float4 a4 = *(const float4*)&As[k][ty * 4];
            float4 b4 = *(const float4*)&Bs[k][tx * 4];
            float am[4] = {a4.x, a4.y, a4.z, a4.w};
            float bn[4] = {b4.x, b4.y, b4.z, b4.w};
#pragma unroll
            for (int i = 0; i < 4; i++)
#pragma unroll
                for (int j = 0; j < 4; j++)
                    acc[i][j] = fmaf(am[i], bn[j], acc[i][j]);
        }
        __syncthreads();
    }

    // fp32 row-major Wh
#pragma unroll
    for (int i = 0; i < 4; i++) {
        float* crow = g_Wh + (size_t)(m0 + ty * 4 + i) * 256 + n0 + tx * 4;
        *(float4*)crow = make_float4(acc[i][0], acc[i][1], acc[i][2], acc[i][3]);
    }

    // transpose through smem, emit half WhT[b][n][k]
#pragma unroll
    for (int i = 0; i < 4; i++)
#pragma unroll
        for (int j = 0; j < 4; j++)
            Cs[tx * 4 + j][ty * 4 + i] = acc[i][j];
    __syncthreads();

    int b  = m0 >> 11;
    int i0 = m0 & 2047;
    int nr = tid >> 2;
    int q  = tid & 3;
    __half* dst = g_WhT + ((size_t)(b * 256 + n0 + nr)) * 2048 + i0 + q * 16;
    uint32_t pk[8];
#pragma unroll
    for (int s = 0; s < 8; s++) {
        __half2 h2 = __floats2half2_rn(Cs[nr][q * 16 + s * 2],
                                       Cs[nr][q * 16 + s * 2 + 1]);
        pk[s] = *(uint32_t*)&h2;
    }
    *(uint4*)(dst)     = make_uint4(pk[0], pk[1], pk[2], pk[3]);
    *(uint4*)(dst + 8) = make_uint4(pk[4], pk[5], pk[6], pk[7]);
}

// ============================================================
// Kernel 2: s1, s2
// ============================================================
__global__ void k_s(const float* __restrict__ a) {
    int row  = blockIdx.x * 8 + (threadIdx.x >> 5);
    int lane = threadIdx.x & 31;
    const float* wh = g_Wh + (size_t)row * 256;

    float v1 = 0.0f, v2 = 0.0f;
#pragma unroll
    for (int k = lane; k < 256; k += 32) {
        float x = wh[k];
        v1 = fmaf(x, a[k],       v1);
        v2 = fmaf(x, a[256 + k], v2);
    }
#pragma unroll
    for (int off = 16; off; off >>= 1) {
        v1 += __shfl_down_sync(0xffffffffu, v1, off);
        v2 += __shfl_down_sync(0xffffffffu, v2, off);
    }
    if (lane == 0) { g_s1[row] = v1; g_s2[row] = v2; }
}

// ============================================================
// Kernel 3: masked-leaky softmax -> normalized half P rows
// ============================================================
__global__ __launch_bounds__(256) void k_softmax(const int* __restrict__ adj) {
    __shared__ float es[2048];
    __shared__ float redm[8];
    __shared__ float redsum[8];

    int i = blockIdx.x;
    int b = blockIdx.y;
    int tid  = threadIdx.x;
    int wid  = tid >> 5;
    int lane = tid & 31;

    const int*   arow = adj + ((size_t)b * 2048 + i) * 2048;
    const float* s2   = g_s2 + (size_t)b * 2048;
    float s1i = g_s1[(size_t)b * 2048 + i];

    float lm = -INFINITY;
#pragma unroll
    for (int j = tid; j < 2048; j += 256) {
        float e = s1i + s2[j];
        e = (e > 0.0f) ? e : LEAKY * e;
        e = arow[j] ? e : NEG_BIG;
        es[j] = e;
        lm = fmaxf(lm, e);
    }
#pragma unroll
    for (int off = 16; off; off >>= 1)
        lm = fmaxf(lm, __shfl_xor_sync(0xffffffffu, lm, off));
    if (lane == 0) redm[wid] = lm;
    __syncthreads();

    float m = redm[0];
#pragma unroll
    for (int w = 1; w < 8; w++) m = fmaxf(m, redm[w]);

    float ls = 0.0f;
#pragma unroll
    for (int j = tid; j < 2048; j += 256) {
        float p = __expf(es[j] - m);
        es[j] = p;
        ls += p;
    }
#pragma unroll
    for (int off = 16; off; off >>= 1)
        ls += __shfl_xor_sync(0xffffffffu, ls, off);
    if (lane == 0) redsum[wid] = ls;
    __syncthreads();

    float sum = 0.0f;
#pragma unroll
    for (int w = 0; w < 8; w++) sum += redsum[w];
    float rinv = 1.0f / sum;

    __half* prow = g_P + ((size_t)b * 2048 + i) * 2048;
#pragma unroll
    for (int j = tid; j < 2048; j += 256)
        prow[j] = __float2half_rn(es[j] * rinv);
}

// ============================================================
// Kernel 4: out = elu(P @ Wh) via fp16 mma m16n8k16, f32 accum.
//   BM=64, BN=256, BK=32. Double-buffered cp.async.
//   Smem: A [64][40] half, B(^T) [256][40] half (stride 40 => 80B,
//   16B aligned rows; 20-word stride => conflict-free LDS.32).
// ============================================================
__device__ __forceinline__ void mma_f16(float* d, const uint32_t* a, const uint32_t* b) {
    asm volatile(
        "mma.sync.aligned.m16n8k16.row.col.f32.f16.f16.f32 "
        "{%0,%1,%2,%3}, {%4,%5,%6,%7}, {%8,%9}, {%0,%1,%2,%3};"
        : "+f"(d[0]), "+f"(d[1]), "+f"(d[2]), "+f"(d[3])
        : "r"(a[0]), "r"(a[1]), "r"(a[2]), "r"(a[3]), "r"(b[0]), "r"(b[1]));
}

#define A_STRIDE 40
#define B_STRIDE 40
#define A_BUF_HALFS (64 * A_STRIDE)     // 2560
#define B_BUF_HALFS (256 * B_STRIDE)    // 10240

__global__ __launch_bounds__(256) void k_av(float* __restrict__ out) {
    extern __shared__ __half sm[];
    __half* Asm = sm;                        // [2][64][40]
    __half* Bsm = sm + 2 * A_BUF_HALFS;      // [2][256][40]

    int b  = blockIdx.y;
    int m0 = blockIdx.x * 64;
    int tid  = threadIdx.x;
    int wid  = tid >> 5, lane = tid & 31;
    int g = lane >> 2, tig = lane & 3;
    int warpM = wid >> 2, warpN = wid & 3;

    const __half* Pb   = g_P   + ((size_t)b * 2048 + m0) * 2048;
    const __half* WhTb = g_WhT + (size_t)b * 256 * 2048;

    // cp.async source/dst precompute
    //   A: 256 chunks of 16B (64 rows x 4), 1 per thread
    int ar = tid >> 2, aq = tid & 3;
    const __half* a_src = Pb + (size_t)ar * 2048 + aq * 8;
    uint32_t a_dst = sptr(Asm + ar * A_STRIDE + aq * 8);
    //   B: 1024 chunks (256 rows x 4), 4 per thread
    const __half* b_src[4]; uint32_t b_dst[4];
#pragma unroll
    for (int p = 0; p < 4; p++) {
        int c = tid + p * 256;
        int nr = c >> 2, q = c & 3;
        b_src[p] = WhTb + (size_t)nr * 2048 + q * 8;
        b_dst[p] = sptr(Bsm + nr * B_STRIDE + q * 8);
    }

    float acc[2][8][4];
#pragma unroll
    for (int mt = 0; mt < 2; mt++)
#pragma unroll
        for (int nt = 0; nt < 8; nt++)
#pragma unroll
            for (int c = 0; c < 4; c++) acc[mt][nt][c] = 0.0f;

    const uint32_t ABUF = A_BUF_HALFS * 2;   // bytes
    const uint32_t BBUF = B_BUF_HALFS * 2;

    auto issue_tile = [&](int k0, int buf) {
        CP_ASYNC16(a_dst + buf * ABUF, a_src + k0);
#pragma unroll
        for (int p = 0; p < 4; p++)
            CP_ASYNC16(b_dst[p] + buf * BBUF, b_src[p] + k0);
        CP_COMMIT();
    };

    issue_tile(0, 0);

#pragma unroll 1
    for (int t = 0; t < 64; t++) {
        int buf = t & 1;
        CP_WAIT0();
        __syncthreads();
        if (t + 1 < 64) issue_tile((t + 1) * 32, buf ^ 1);

        const __half* Ab = Asm + buf * A_BUF_HALFS;
        const __half* Bb = Bsm + buf * B_BUF_HALFS;

#pragma unroll
        for (int kc = 0; kc < 2; kc++) {
            int kb = kc * 16;
            uint32_t afr[2][4];
#pragma unroll
            for (int mt = 0; mt < 2; mt++) {
                int mr = warpM * 32 + mt * 16;
                afr[mt][0] = *(const uint32_t*)(Ab + (mr + g    ) * A_STRIDE + kb + 2 * tig);
                afr[mt][1] = *(const uint32_t*)(Ab + (mr + g + 8) * A_STRIDE + kb + 2 * tig);
                afr[mt][2] = *(const uint32_t*)(Ab + (mr + g    ) * A_STRIDE + kb + 2 * tig + 8);
                afr[mt][3] = *(const uint32_t*)(Ab + (mr + g + 8) * A_STRIDE + kb + 2 * tig + 8);
            }
            uint32_t bfr[8][2];
#pragma unroll
            for (int nt = 0; nt < 8; nt++) {
                int nc = warpN * 64 + nt * 8 + g;
                bfr[nt][0] = *(const uint32_t*)(Bb + nc * B_STRIDE + kb + 2 * tig);
                bfr[nt][1] = *(const uint32_t*)(Bb + nc * B_STRIDE + kb + 2 * tig + 8);
            }
#pragma unroll
            for (int mt = 0; mt < 2; mt++)
#pragma unroll
                for (int nt = 0; nt < 8; nt++)
                    mma_f16(acc[mt][nt], afr[mt], bfr[nt]);
        }
        __syncthreads();
    }

    // epilogue: ELU + store
#pragma unroll
    for (int mt = 0; mt < 2; mt++) {
#pragma unroll
        for (int nt = 0; nt < 8; nt++) {
            int m = m0 + warpM * 32 + mt * 16 + g;
            int n = warpN * 64 + nt * 8 + 2 * tig;
            float c0 = acc[mt][nt][0], c1 = acc[mt][nt][1];
            float c2 = acc[mt][nt][2], c3 = acc[mt][nt][3];
            c0 = (c0 > 0.0f) ? c0 : expm1f(c0);
            c1 = (c1 > 0.0f) ? c1 : expm1f(c1);
            c2 = (c2 > 0.0f) ? c2 : expm1f(c2);
            c3 = (c3 > 0.0f) ? c3 : expm1f(c3);
            float* o0 = out + ((size_t)b * 2048 + m) * 256 + n;
            float* o1 = out + ((size_t)b * 2048 + m + 8) * 256 + n;
            *(float2*)o0 = make_float2(c0, c1);
            *(float2*)o1 = make_float2(c2, c3);
        }
    }
}

// ============================================================
extern "C" void kernel_launch(void* const* d_in, const int* in_sizes, int n_in,
                              void* d_out, int out_size) {
    const float* h   = (const float*)d_in[0];
    const int*   adj = (const int*)  d_in[1];
    const float* W   = (const float*)d_in[2];
    const float* a   = (const float*)d_in[3];
    float* out = (float*)d_out;

    const int AV_SMEM = 2 * (A_BUF_HALFS + B_BUF_HALFS) * 2;  // 51200 B
    static int attr_done = 0;
    if (!attr_done) {
        cudaFuncSetAttribute(k_av, cudaFuncAttributeMaxDynamicSharedMemorySize,
                             AV_SMEM);
        attr_done = 1;
    }

    dim3 g1(16384 / 64, 256 / 64);
    k_gemm<<<g1, 256>>>(h, W);

    k_s<<<16384 / 8, 256>>>(a);

    dim3 g3(2048, 8);
    k_softmax<<<g3, 256>>>(adj);

    dim3 g4(2048 / 64, 8);
    k_av<<<g4, 256, AV_SMEM>>>(out);
}

// round 6
// speedup vs baseline: 1.6603x; 1.0291x over previous
#include <cuda_runtime.h>
#include <cuda_fp16.h>
#include <cstdint>

#define NEG_BIG (-9000000000000000.0f)
#define LEAKY 0.2f

// ---- scratch (static device globals; no runtime allocation) ----
__device__ float  g_Wh  [8ul * 2048 * 256];    // fp32 Wh (exact, for s1/s2)
__device__ __half g_WhT [8ul * 256 * 2048];    // [b][n][k] half (B operand)
__device__ __half g_P   [8ul * 2048 * 2048];   // normalized attention, half
__device__ float  g_s1  [8 * 2048];
__device__ float  g_s2  [8 * 2048];

__device__ __forceinline__ unsigned sptr(const void* p) {
    return (unsigned)__cvta_generic_to_shared(p);
}
#define CP_ASYNC16(dst, src) \
    asm volatile("cp.async.cg.shared.global [%0], [%1], 16;" :: "r"(dst), "l"(src))
#define CP_COMMIT() asm volatile("cp.async.commit_group;")
#define CP_WAIT0()  asm volatile("cp.async.wait_group 0;")
#define CP_WAIT1()  asm volatile("cp.async.wait_group 1;")

__device__ __forceinline__ void ldsm_x4(uint32_t& r0, uint32_t& r1,
                                        uint32_t& r2, uint32_t& r3,
                                        uint32_t addr) {
    asm volatile("ldmatrix.sync.aligned.m8n8.x4.shared.b16 {%0,%1,%2,%3}, [%4];"
                 : "=r"(r0), "=r"(r1), "=r"(r2), "=r"(r3) : "r"(addr));
}

// ============================================================
// Kernel 1: Wh = h @ W^T (fp32 SIMT, 128x128 tile, 8x8/thread)
//   Epilogue writes fp32 Wh and half transposed WhT[b][n][k]
//   directly from registers.
// ============================================================
__global__ __launch_bounds__(256) void k_gemm(const float* __restrict__ A,
                                              const float* __restrict__ Bm) {
    __shared__ float As[16][132];
    __shared__ float Bs[16][132];

    int tid = threadIdx.x;
    int tx = tid & 15, ty = tid >> 4;
    int m0 = blockIdx.x * 128;
    int n0 = blockIdx.y * 128;

    int lr = tid >> 1;              // 0..127
    int lc = (tid & 1) * 8;         // 0 or 8
    const float* Aptr = A  + (size_t)(m0 + lr) * 256 + lc;
    const float* Bptr = Bm + (size_t)(n0 + lr) * 256 + lc;

    float acc[8][8];
#pragma unroll
    for (int i = 0; i < 8; i++)
#pragma unroll
        for (int j = 0; j < 8; j++) acc[i][j] = 0.0f;

    for (int k0 = 0; k0 < 256; k0 += 16) {
        float4 a0 = *(const float4*)(Aptr + k0);
        float4 a1 = *(const float4*)(Aptr + k0 + 4);
        float4 b0 = *(const float4*)(Bptr + k0);
        float4 b1 = *(const float4*)(Bptr + k0 + 4);
        As[lc + 0][lr] = a0.x; As[lc + 1][lr] = a0.y;
        As[lc + 2][lr] = a0.z; As[lc + 3][lr] = a0.w;
        As[lc + 4][lr] = a1.x; As[lc + 5][lr] = a1.y;
        As[lc + 6][lr] = a1.z; As[lc + 7][lr] = a1.w;
        Bs[lc + 0][lr] = b0.x; Bs[lc + 1][lr] = b0.y;
        Bs[lc + 2][lr] = b0.z; Bs[lc + 3][lr] = b0.w;
        Bs[lc + 4][lr] = b1.x; Bs[lc + 5][lr] = b1.y;
        Bs[lc + 6][lr] = b1.z; Bs[lc + 7][lr] = b1.w;
        __syncthreads();

#pragma unroll
        for (int k = 0; k < 16; k++) {
            float4 av0 = *(const float4*)&As[k][ty * 8];
            float4 av1 = *(const float4*)&As[k][ty * 8 + 4];
            float4 bv0 = *(const float4*)&Bs[k][tx * 8];
            float4 bv1 = *(const float4*)&Bs[k][tx * 8 + 4];
            float am[8] = {av0.x, av0.y, av0.z, av0.w, av1.x, av1.y, av1.z, av1.w};
            float bn[8] = {bv0.x, bv0.y, bv0.z, bv0.w, bv1.x, bv1.y, bv1.z, bv1.w};
#pragma unroll
            for (int i = 0; i < 8; i++)
#pragma unroll
                for (int j = 0; j < 8; j++)
                    acc[i][j] = fmaf(am[i], bn[j], acc[i][j]);
        }
        __syncthreads();
    }

    // fp32 Wh rows
#pragma unroll
    for (int i = 0; i < 8; i++) {
        float* crow = g_Wh + (size_t)(m0 + ty * 8 + i) * 256 + n0 + tx * 8;
        *(float4*)(crow)     = make_float4(acc[i][0], acc[i][1], acc[i][2], acc[i][3]);
        *(float4*)(crow + 4) = make_float4(acc[i][4], acc[i][5], acc[i][6], acc[i][7]);
    }

    // half WhT[b][n][m] directly from registers (16B per n-row)
    int b  = m0 >> 11;
    int i0 = m0 & 2047;
#pragma unroll
    for (int j = 0; j < 8; j++) {
        __half2 h0 = __floats2half2_rn(acc[0][j], acc[1][j]);
        __half2 h1 = __floats2half2_rn(acc[2][j], acc[3][j]);
        __half2 h2 = __floats2half2_rn(acc[4][j], acc[5][j]);
        __half2 h3 = __floats2half2_rn(acc[6][j], acc[7][j]);
        uint4 v = make_uint4(*(uint32_t*)&h0, *(uint32_t*)&h1,
                             *(uint32_t*)&h2, *(uint32_t*)&h3);
        *(uint4*)(g_WhT + ((size_t)(b * 256 + n0 + tx * 8 + j)) * 2048
                  + i0 + ty * 8) = v;
    }
}

// ============================================================
// Kernel 2: s1, s2
// ============================================================
__global__ void k_s(const float* __restrict__ a) {
    int row  = blockIdx.x * 8 + (threadIdx.x >> 5);
    int lane = threadIdx.x & 31;
    const float* wh = g_Wh + (size_t)row * 256;

    float v1 = 0.0f, v2 = 0.0f;
#pragma unroll
    for (int k = lane; k < 256; k += 32) {
        float x = wh[k];
        v1 = fmaf(x, a[k],       v1);
        v2 = fmaf(x, a[256 + k], v2);
    }
#pragma unroll
    for (int off = 16; off; off >>= 1) {
        v1 += __shfl_down_sync(0xffffffffu, v1, off);
        v2 += __shfl_down_sync(0xffffffffu, v2, off);
    }
    if (lane == 0) { g_s1[row] = v1; g_s2[row] = v2; }
}

// ============================================================
// Kernel 3: masked-leaky softmax -> normalized half P rows
// ============================================================
__global__ __launch_bounds__(256) void k_softmax(const int* __restrict__ adj) {
    __shared__ float es[2048];
    __shared__ float redm[8];
    __shared__ float redsum[8];

    int i = blockIdx.x;
    int b = blockIdx.y;
    int tid  = threadIdx.x;
    int wid  = tid >> 5;
    int lane = tid & 31;

    const int*   arow = adj + ((size_t)b * 2048 + i) * 2048;
    const float* s2   = g_s2 + (size_t)b * 2048;
    float s1i = g_s1[(size_t)b * 2048 + i];

    float lm = -INFINITY;
#pragma unroll
    for (int j = tid; j < 2048; j += 256) {
        float e = s1i + s2[j];
        e = (e > 0.0f) ? e : LEAKY * e;
        e = arow[j] ? e : NEG_BIG;
        es[j] = e;
        lm = fmaxf(lm, e);
    }
#pragma unroll
    for (int off = 16; off; off >>= 1)
        lm = fmaxf(lm, __shfl_xor_sync(0xffffffffu, lm, off));
    if (lane == 0) redm[wid] = lm;
    __syncthreads();

    float m = redm[0];
#pragma unroll
    for (int w = 1; w < 8; w++) m = fmaxf(m, redm[w]);

    float ls = 0.0f;
#pragma unroll
    for (int j = tid; j < 2048; j += 256) {
        float p = __expf(es[j] - m);
        es[j] = p;
        ls += p;
    }
#pragma unroll
    for (int off = 16; off; off >>= 1)
        ls += __shfl_xor_sync(0xffffffffu, ls, off);
    if (lane == 0) redsum[wid] = ls;
    __syncthreads();

    float sum = 0.0f;
#pragma unroll
    for (int w = 0; w < 8; w++) sum += redsum[w];
    float rinv = 1.0f / sum;

    __half* prow = g_P + ((size_t)b * 2048 + i) * 2048;
#pragma unroll
    for (int j = tid; j < 2048; j += 256)
        prow[j] = __float2half_rn(es[j] * rinv);
}

// ============================================================
// Kernel 4: out = elu(P @ Wh), fp16 mma m16n8k16 + ldmatrix.x4,
//   BM=64, BN=256, BK=32. 3-stage cp.async pipeline.
// ============================================================
__device__ __forceinline__ void mma_f16(float* d, const uint32_t* a, const uint32_t* b) {
    asm volatile(
        "mma.sync.aligned.m16n8k16.row.col.f32.f16.f16.f32 "
        "{%0,%1,%2,%3}, {%4,%5,%6,%7}, {%8,%9}, {%0,%1,%2,%3};"
        : "+f"(d[0]), "+f"(d[1]), "+f"(d[2]), "+f"(d[3])
        : "r"(a[0]), "r"(a[1]), "r"(a[2]), "r"(a[3]), "r"(b[0]), "r"(b[1]));
}

#define A_STRIDE 40
#define B_STRIDE 40
#define A_BUF_HALFS (64 * A_STRIDE)     // 2560
#define B_BUF_HALFS (256 * B_STRIDE)    // 10240
#define NSTAGE 3

__global__ __launch_bounds__(256) void k_av(float* __restrict__ out) {
    extern __shared__ __half sm[];
    __half* Asm = sm;                          // [3][64][40]
    __half* Bsm = sm + NSTAGE * A_BUF_HALFS;   // [3][256][40]

    int b  = blockIdx.y;
    int m0 = blockIdx.x * 64;
    int tid  = threadIdx.x;
    int wid  = tid >> 5, lane = tid & 31;
    int g = lane >> 2, tig = lane & 3;
    int warpM = wid >> 2, warpN = wid & 3;

    const __half* Pb   = g_P   + ((size_t)b * 2048 + m0) * 2048;
    const __half* WhTb = g_WhT + (size_t)b * 256 * 2048;

    // cp.async: A 256 chunks (1/thread), B 1024 chunks (4/thread)
    int ar = tid >> 2, aq = tid & 3;
    const __half* a_src = Pb + (size_t)ar * 2048 + aq * 8;
    uint32_t a_dst = sptr(Asm + ar * A_STRIDE + aq * 8);
    const __half* b_src[4]; uint32_t b_dst[4];
#pragma unroll
    for (int p = 0; p < 4; p++) {
        int c = tid + p * 256;
        int nr = c >> 2, q = c & 3;
        b_src[p] = WhTb + (size_t)nr * 2048 + q * 8;
        b_dst[p] = sptr(Bsm + nr * B_STRIDE + q * 8);
    }

    // ldmatrix lane addresses (byte offsets within a stage)
    uint32_t a_ld[2][2], b_ld[4][2];
    {
        int arow = lane & 15;
        int akh  = (lane >> 4) * 8;
        int brow = (lane & 7) + ((lane >> 4) & 1) * 8;
        int bkh  = ((lane >> 3) & 1) * 8;
#pragma unroll
        for (int kc = 0; kc < 2; kc++) {
#pragma unroll
            for (int mt = 0; mt < 2; mt++)
                a_ld[mt][kc] = sptr(Asm +
                    (warpM * 32 + mt * 16 + arow) * A_STRIDE + kc * 16 + akh);
#pragma unroll
            for (int p = 0; p < 4; p++)
                b_ld[p][kc] = sptr(Bsm +
                    (warpN * 64 + p * 16 + brow) * B_STRIDE + kc * 16 + bkh);
        }
    }

    float acc[2][8][4];
#pragma unroll
    for (int mt = 0; mt < 2; mt++)
#pragma unroll
        for (int nt = 0; nt < 8; nt++)
#pragma unroll
            for (int c = 0; c < 4; c++) acc[mt][nt][c] = 0.0f;

    const uint32_t ABUF = A_BUF_HALFS * 2;   // stage stride, bytes
    const uint32_t BBUF = B_BUF_HALFS * 2;

    auto issue_tile = [&](int k0, int st) {
        CP_ASYNC16(a_dst + st * ABUF, a_src + k0);
#pragma unroll
        for (int p = 0; p < 4; p++)
            CP_ASYNC16(b_dst[p] + st * BBUF, b_src[p] + k0);
        CP_COMMIT();
    };

    issue_tile(0, 0);
    issue_tile(32, 1);

#pragma unroll 1
    for (int t = 0; t < 64; t++) {
        int st = t % NSTAGE;
        if (t + 2 < 64) { CP_WAIT1(); } else { CP_WAIT0(); }
        __syncthreads();
        if (t + 2 < 64) issue_tile((t + 2) * 32, (t + 2) % NSTAGE);

        uint32_t ab = st * ABUF;
        uint32_t bb = st * BBUF;

#pragma unroll
        for (int kc = 0; kc < 2; kc++) {
            uint32_t afr[2][4];
#pragma unroll
            for (int mt = 0; mt < 2; mt++)
                ldsm_x4(afr[mt][0], afr[mt][1], afr[mt][2], afr[mt][3],
                        a_ld[mt][kc] + ab);
            uint32_t bfr[8][2];
#pragma unroll
            for (int p = 0; p < 4; p++) {
                uint32_t r0, r1, r2, r3;
                ldsm_x4(r0, r1, r2, r3, b_ld[p][kc] + bb);
                bfr[2 * p][0] = r0;     bfr[2 * p][1] = r1;
                bfr[2 * p + 1][0] = r2; bfr[2 * p + 1][1] = r3;
            }
#pragma unroll
            for (int mt = 0; mt < 2; mt++)
#pragma unroll
                for (int nt = 0; nt < 8; nt++)
                    mma_f16(acc[mt][nt], afr[mt], bfr[nt]);
        }
        __syncthreads();
    }

    // epilogue: ELU + store
#pragma unroll
    for (int mt = 0; mt < 2; mt++) {
#pragma unroll
        for (int nt = 0; nt < 8; nt++) {
            int m = m0 + warpM * 32 + mt * 16 + g;
            int n = warpN * 64 + nt * 8 + 2 * tig;
            float c0 = acc[mt][nt][0], c1 = acc[mt][nt][1];
            float c2 = acc[mt][nt][2], c3 = acc[mt][nt][3];
            c0 = (c0 > 0.0f) ? c0 : expm1f(c0);
            c1 = (c1 > 0.0f) ? c1 : expm1f(c1);
            c2 = (c2 > 0.0f) ? c2 : expm1f(c2);
            c3 = (c3 > 0.0f) ? c3 : expm1f(c3);
            float* o0 = out + ((size_t)b * 2048 + m) * 256 + n;
            float* o1 = out + ((size_t)b * 2048 + m + 8) * 256 + n;
            *(float2*)o0 = make_float2(c0, c1);
            *(float2*)o1 = make_float2(c2, c3);
        }
    }
}

// ============================================================
extern "C" void kernel_launch(void* const* d_in, const int* in_sizes, int n_in,
                              void* d_out, int out_size) {
    const float* h   = (const float*)d_in[0];
    const int*   adj = (const int*)  d_in[1];
    const float* W   = (const float*)d_in[2];
    const float* a   = (const float*)d_in[3];
    float* out = (float*)d_out;

    const int AV_SMEM = NSTAGE * (A_BUF_HALFS + B_BUF_HALFS) * 2;  // 76800 B
    static int attr_done = 0;
    if (!attr_done) {
        cudaFuncSetAttribute(k_av, cudaFuncAttributeMaxDynamicSharedMemorySize,
                             AV_SMEM);
        attr_done = 1;
    }

    dim3 g1(16384 / 128, 256 / 128);          // 128 x 2
    k_gemm<<<g1, 256>>>(h, W);

    k_s<<<16384 / 8, 256>>>(a);

    dim3 g3(2048, 8);
    k_softmax<<<g3, 256>>>(adj);

    dim3 g4(2048 / 64, 8);
    k_av<<<g4, 256, AV_SMEM>>>(out);
}

// round 7
// speedup vs baseline: 1.7075x; 1.0284x over previous
#include <cuda_runtime.h>
#include <cuda_fp16.h>
#include <cstdint>

#define NEG_BIG (-9000000000000000.0f)
#define LEAKY 0.2f

// ---- scratch (static device globals; no runtime allocation) ----
__device__ float  g_Wh  [8ul * 2048 * 256];    // fp32 Wh (exact, for s1/s2)
__device__ __half g_WhT [8ul * 256 * 2048];    // [b][n][k] half (B operand)
__device__ __half g_P   [8ul * 2048 * 2048];   // normalized attention, half
__device__ float  g_s1  [8 * 2048];
__device__ float  g_s2  [8 * 2048];

__device__ __forceinline__ unsigned sptr(const void* p) {
    return (unsigned)__cvta_generic_to_shared(p);
}
#define CP_ASYNC16(dst, src) \
    asm volatile("cp.async.cg.shared.global [%0], [%1], 16;" :: "r"(dst), "l"(src))
#define CP_COMMIT() asm volatile("cp.async.commit_group;")
#define CP_WAIT0()  asm volatile("cp.async.wait_group 0;")
#define CP_WAIT1()  asm volatile("cp.async.wait_group 1;")
#define CP_WAIT2()  asm volatile("cp.async.wait_group 2;")

__device__ __forceinline__ void ldsm_x4(uint32_t& r0, uint32_t& r1,
                                        uint32_t& r2, uint32_t& r3,
                                        uint32_t addr) {
    asm volatile("ldmatrix.sync.aligned.m8n8.x4.shared.b16 {%0,%1,%2,%3}, [%4];"
                 : "=r"(r0), "=r"(r1), "=r"(r2), "=r"(r3) : "r"(addr));
}

// ============================================================
// Kernel 1: Wh = h @ W^T (fp32 SIMT, 128x128 tile, 8x8/thread)
// ============================================================
__global__ __launch_bounds__(256) void k_gemm(const float* __restrict__ A,
                                              const float* __restrict__ Bm) {
    __shared__ float As[16][132];
    __shared__ float Bs[16][132];

    int tid = threadIdx.x;
    int tx = tid & 15, ty = tid >> 4;
    int m0 = blockIdx.x * 128;
    int n0 = blockIdx.y * 128;

    int lr = tid >> 1;
    int lc = (tid & 1) * 8;
    const float* Aptr = A  + (size_t)(m0 + lr) * 256 + lc;
    const float* Bptr = Bm + (size_t)(n0 + lr) * 256 + lc;

    float acc[8][8];
#pragma unroll
    for (int i = 0; i < 8; i++)
#pragma unroll
        for (int j = 0; j < 8; j++) acc[i][j] = 0.0f;

    for (int k0 = 0; k0 < 256; k0 += 16) {
        float4 a0 = *(const float4*)(Aptr + k0);
        float4 a1 = *(const float4*)(Aptr + k0 + 4);
        float4 b0 = *(const float4*)(Bptr + k0);
        float4 b1 = *(const float4*)(Bptr + k0 + 4);
        As[lc + 0][lr] = a0.x; As[lc + 1][lr] = a0.y;
        As[lc + 2][lr] = a0.z; As[lc + 3][lr] = a0.w;
        As[lc + 4][lr] = a1.x; As[lc + 5][lr] = a1.y;
        As[lc + 6][lr] = a1.z; As[lc + 7][lr] = a1.w;
        Bs[lc + 0][lr] = b0.x; Bs[lc + 1][lr] = b0.y;
        Bs[lc + 2][lr] = b0.z; Bs[lc + 3][lr] = b0.w;
        Bs[lc + 4][lr] = b1.x; Bs[lc + 5][lr] = b1.y;
        Bs[lc + 6][lr] = b1.z; Bs[lc + 7][lr] = b1.w;
        __syncthreads();

#pragma unroll
        for (int k = 0; k < 16; k++) {
            float4 av0 = *(const float4*)&As[k][ty * 8];
            float4 av1 = *(const float4*)&As[k][ty * 8 + 4];
            float4 bv0 = *(const float4*)&Bs[k][tx * 8];
            float4 bv1 = *(const float4*)&Bs[k][tx * 8 + 4];
            float am[8] = {av0.x, av0.y, av0.z, av0.w, av1.x, av1.y, av1.z, av1.w};
            float bn[8] = {bv0.x, bv0.y, bv0.z, bv0.w, bv1.x, bv1.y, bv1.z, bv1.w};
#pragma unroll
            for (int i = 0; i < 8; i++)
#pragma unroll
                for (int j = 0; j < 8; j++)
                    acc[i][j] = fmaf(am[i], bn[j], acc[i][j]);
        }
        __syncthreads();
    }

#pragma unroll
    for (int i = 0; i < 8; i++) {
        float* crow = g_Wh + (size_t)(m0 + ty * 8 + i) * 256 + n0 + tx * 8;
        *(float4*)(crow)     = make_float4(acc[i][0], acc[i][1], acc[i][2], acc[i][3]);
        *(float4*)(crow + 4) = make_float4(acc[i][4], acc[i][5], acc[i][6], acc[i][7]);
    }

    int b  = m0 >> 11;
    int i0 = m0 & 2047;
#pragma unroll
    for (int j = 0; j < 8; j++) {
        __half2 h0 = __floats2half2_rn(acc[0][j], acc[1][j]);
        __half2 h1 = __floats2half2_rn(acc[2][j], acc[3][j]);
        __half2 h2 = __floats2half2_rn(acc[4][j], acc[5][j]);
        __half2 h3 = __floats2half2_rn(acc[6][j], acc[7][j]);
        uint4 v = make_uint4(*(uint32_t*)&h0, *(uint32_t*)&h1,
                             *(uint32_t*)&h2, *(uint32_t*)&h3);
        *(uint4*)(g_WhT + ((size_t)(b * 256 + n0 + tx * 8 + j)) * 2048
                  + i0 + ty * 8) = v;
    }
}

// ============================================================
// Kernel 2: s1, s2
// ============================================================
__global__ void k_s(const float* __restrict__ a) {
    int row  = blockIdx.x * 8 + (threadIdx.x >> 5);
    int lane = threadIdx.x & 31;
    const float* wh = g_Wh + (size_t)row * 256;

    float v1 = 0.0f, v2 = 0.0f;
#pragma unroll
    for (int k = lane; k < 256; k += 32) {
        float x = wh[k];
        v1 = fmaf(x, a[k],       v1);
        v2 = fmaf(x, a[256 + k], v2);
    }
#pragma unroll
    for (int off = 16; off; off >>= 1) {
        v1 += __shfl_down_sync(0xffffffffu, v1, off);
        v2 += __shfl_down_sync(0xffffffffu, v2, off);
    }
    if (lane == 0) { g_s1[row] = v1; g_s2[row] = v2; }
}

// ============================================================
// Kernel 3: masked-leaky softmax -> normalized half P rows
//   int4 adjacency loads, half2 stores.
// ============================================================
__global__ __launch_bounds__(256) void k_softmax(const int* __restrict__ adj) {
    __shared__ float es[2048];
    __shared__ float redm[8];
    __shared__ float redsum[8];

    int i = blockIdx.x;
    int b = blockIdx.y;
    int tid  = threadIdx.x;
    int wid  = tid >> 5;
    int lane = tid & 31;

    const int4*  arow4 = (const int4*)(adj + ((size_t)b * 2048 + i) * 2048);
    const float* s2    = g_s2 + (size_t)b * 2048;
    float s1i = g_s1[(size_t)b * 2048 + i];

    float lm = -INFINITY;
#pragma unroll
    for (int jv = tid; jv < 512; jv += 256) {
        int4   av  = arow4[jv];
        float4 s2v = *(const float4*)(s2 + jv * 4);
        float e0 = s1i + s2v.x, e1 = s1i + s2v.y;
        float e2 = s1i + s2v.z, e3 = s1i + s2v.w;
        e0 = (e0 > 0.0f) ? e0 : LEAKY * e0;
        e1 = (e1 > 0.0f) ? e1 : LEAKY * e1;
        e2 = (e2 > 0.0f) ? e2 : LEAKY * e2;
        e3 = (e3 > 0.0f) ? e3 : LEAKY * e3;
        e0 = av.x ? e0 : NEG_BIG;
        e1 = av.y ? e1 : NEG_BIG;
        e2 = av.z ? e2 : NEG_BIG;
        e3 = av.w ? e3 : NEG_BIG;
        *(float4*)&es[jv * 4] = make_float4(e0, e1, e2, e3);
        lm = fmaxf(lm, fmaxf(fmaxf(e0, e1), fmaxf(e2, e3)));
    }
#pragma unroll
    for (int off = 16; off; off >>= 1)
        lm = fmaxf(lm, __shfl_xor_sync(0xffffffffu, lm, off));
    if (lane == 0) redm[wid] = lm;
    __syncthreads();

    float m = redm[0];
#pragma unroll
    for (int w = 1; w < 8; w++) m = fmaxf(m, redm[w]);

    float ls = 0.0f;
#pragma unroll
    for (int j = tid; j < 2048; j += 256) {
        float p = __expf(es[j] - m);
        es[j] = p;
        ls += p;
    }
#pragma unroll
    for (int off = 16; off; off >>= 1)
        ls += __shfl_xor_sync(0xffffffffu, ls, off);
    if (lane == 0) redsum[wid] = ls;
    __syncthreads();

    float sum = 0.0f;
#pragma unroll
    for (int w = 0; w < 8; w++) sum += redsum[w];
    float rinv = 1.0f / sum;

    __half2* prow2 = (__half2*)(g_P + ((size_t)b * 2048 + i) * 2048);
#pragma unroll
    for (int jv = tid; jv < 1024; jv += 256)
        prow2[jv] = __floats2half2_rn(es[jv * 2] * rinv, es[jv * 2 + 1] * rinv);
}

// ============================================================
// Kernel 4: out = elu(P @ Wh), fp16 mma m16n8k16 + ldmatrix.x4.
//   BM=64, BN=128, BK=32, NSTAGE=4, 3-deep cp.async lookahead.
//   Grid 512 CTAs, target 3 CTAs/SM.
// ============================================================
__device__ __forceinline__ void mma_f16(float* d, const uint32_t* a, const uint32_t* b) {
    asm volatile(
        "mma.sync.aligned.m16n8k16.row.col.f32.f16.f16.f32 "
        "{%0,%1,%2,%3}, {%4,%5,%6,%7}, {%8,%9}, {%0,%1,%2,%3};"
        : "+f"(d[0]), "+f"(d[1]), "+f"(d[2]), "+f"(d[3])
        : "r"(a[0]), "r"(a[1]), "r"(a[2]), "r"(a[3]), "r"(b[0]), "r"(b[1]));
}

#define A_STRIDE 40
#define B_STRIDE 40
#define A_BUF_HALFS (64  * A_STRIDE)    // 2560
#define B_BUF_HALFS (128 * B_STRIDE)    // 5120
#define NSTAGE 4

__global__ __launch_bounds__(256, 3) void k_av(float* __restrict__ out) {
    extern __shared__ __half sm[];
    __half* Asm = sm;                          // [4][64][40]
    __half* Bsm = sm + NSTAGE * A_BUF_HALFS;   // [4][128][40]

    int b  = blockIdx.y >> 1;
    int n0 = (blockIdx.y & 1) * 128;
    int m0 = blockIdx.x * 64;
    int tid  = threadIdx.x;
    int wid  = tid >> 5, lane = tid & 31;
    int g = lane >> 2, tig = lane & 3;
    int warpM = wid >> 2, warpN = wid & 3;     // 2 x 4 warps -> 32x32 tiles

    const __half* Pb   = g_P   + ((size_t)b * 2048 + m0) * 2048;
    const __half* WhTb = g_WhT + ((size_t)b * 256 + n0) * 2048;

    // cp.async: A 256 chunks (1/thread), B 512 chunks (2/thread)
    int ar = tid >> 2, aq = tid & 3;
    const __half* a_src = Pb + (size_t)ar * 2048 + aq * 8;
    uint32_t a_dst = sptr(Asm + ar * A_STRIDE + aq * 8);
    const __half* b_src[2]; uint32_t b_dst[2];
#pragma unroll
    for (int p = 0; p < 2; p++) {
        int c = tid + p * 256;
        int nr = c >> 2, q = c & 3;
        b_src[p] = WhTb + (size_t)nr * 2048 + q * 8;
        b_dst[p] = sptr(Bsm + nr * B_STRIDE + q * 8);
    }

    // ldmatrix lane addresses
    uint32_t a_ld[2][2], b_ld[2][2];
    {
        int arow = lane & 15;
        int akh  = (lane >> 4) * 8;
        int brow = (lane & 7) + ((lane >> 4) & 1) * 8;
        int bkh  = ((lane >> 3) & 1) * 8;
#pragma unroll
        for (int kc = 0; kc < 2; kc++) {
#pragma unroll
            for (int mt = 0; mt < 2; mt++)
                a_ld[mt][kc] = sptr(Asm +
                    (warpM * 32 + mt * 16 + arow) * A_STRIDE + kc * 16 + akh);
#pragma unroll
            for (int p = 0; p < 2; p++)
                b_ld[p][kc] = sptr(Bsm +
                    (warpN * 32 + p * 16 + brow) * B_STRIDE + kc * 16 + bkh);
        }
    }

    float acc[2][4][4];
#pragma unroll
    for (int mt = 0; mt < 2; mt++)
#pragma unroll
        for (int nt = 0; nt < 4; nt++)
#pragma unroll
            for (int c = 0; c < 4; c++) acc[mt][nt][c] = 0.0f;

    const uint32_t ABUF = A_BUF_HALFS * 2;
    const uint32_t BBUF = B_BUF_HALFS * 2;

    auto issue_tile = [&](int k0, int st) {
        CP_ASYNC16(a_dst + st * ABUF, a_src + k0);
#pragma unroll
        for (int p = 0; p < 2; p++)
            CP_ASYNC16(b_dst[p] + st * BBUF, b_src[p] + k0);
        CP_COMMIT();
    };

    issue_tile(0, 0);
    issue_tile(32, 1);
    issue_tile(64, 2);

#pragma unroll 1
    for (int t = 0; t < 64; t++) {
        int st = t & 3;
        if (t + 3 < 64)      { CP_WAIT2(); }
        else if (t + 2 < 64) { CP_WAIT1(); }
        else                 { CP_WAIT0(); }
        __syncthreads();
        if (t + 3 < 64) issue_tile((t + 3) * 32, (t + 3) & 3);

        uint32_t ab = st * ABUF;
        uint32_t bb = st * BBUF;

#pragma unroll
        for (int kc = 0; kc < 2; kc++) {
            uint32_t afr[2][4];
#pragma unroll
            for (int mt = 0; mt < 2; mt++)
                ldsm_x4(afr[mt][0], afr[mt][1], afr[mt][2], afr[mt][3],
                        a_ld[mt][kc] + ab);
            uint32_t bfr[4][2];
#pragma unroll
            for (int p = 0; p < 2; p++) {
                uint32_t r0, r1, r2, r3;
                ldsm_x4(r0, r1, r2, r3, b_ld[p][kc] + bb);
                bfr[2 * p][0] = r0;     bfr[2 * p][1] = r1;
                bfr[2 * p + 1][0] = r2; bfr[2 * p + 1][1] = r3;
            }
#pragma unroll
            for (int mt = 0; mt < 2; mt++)
#pragma unroll
                for (int nt = 0; nt < 4; nt++)
                    mma_f16(acc[mt][nt], afr[mt], bfr[nt]);
        }
        __syncthreads();
    }

    // epilogue: ELU + store
#pragma unroll
    for (int mt = 0; mt < 2; mt++) {
#pragma unroll
        for (int nt = 0; nt < 4; nt++) {
            int m = m0 + warpM * 32 + mt * 16 + g;
            int n = n0 + warpN * 32 + nt * 8 + 2 * tig;
            float c0 = acc[mt][nt][0], c1 = acc[mt][nt][1];
            float c2 = acc[mt][nt][2], c3 = acc[mt][nt][3];
            c0 = (c0 > 0.0f) ? c0 : expm1f(c0);
            c1 = (c1 > 0.0f) ? c1 : expm1f(c1);
            c2 = (c2 > 0.0f) ? c2 : expm1f(c2);
            c3 = (c3 > 0.0f) ? c3 : expm1f(c3);
            float* o0 = out + ((size_t)b * 2048 + m) * 256 + n;
            float* o1 = out + ((size_t)b * 2048 + m + 8) * 256 + n;
            *(float2*)o0 = make_float2(c0, c1);
            *(float2*)o1 = make_float2(c2, c3);
        }
    }
}

// ============================================================
extern "C" void kernel_launch(void* const* d_in, const int* in_sizes, int n_in,
                              void* d_out, int out_size) {
    const float* h   = (const float*)d_in[0];
    const int*   adj = (const int*)  d_in[1];
    const float* W   = (const float*)d_in[2];
    const float* a   = (const float*)d_in[3];
    float* out = (float*)d_out;

    const int AV_SMEM = NSTAGE * (A_BUF_HALFS + B_BUF_HALFS) * 2;  // 61440 B
    static int attr_done = 0;
    if (!attr_done) {
        cudaFuncSetAttribute(k_av, cudaFuncAttributeMaxDynamicSharedMemorySize,
                             AV_SMEM);
        attr_done = 1;
    }

    dim3 g1(16384 / 128, 256 / 128);          // 128 x 2
    k_gemm<<<g1, 256>>>(h, W);

    k_s<<<16384 / 8, 256>>>(a);

    dim3 g3(2048, 8);
    k_softmax<<<g3, 256>>>(adj);

    dim3 g4(2048 / 64, 16);                   // 32 x 16 = 512 CTAs
    k_av<<<g4, 256, AV_SMEM>>>(out);
}